// round 2
// baseline (speedup 1.0000x reference)
#include <cuda_runtime.h>
#include <cuda_bf16.h>
#include <math.h>

// Problem constants
#define BB 8
#define SS 4096
#define DD 512
#define HH 512
#define MM (BB * SS)       // 32768 rows
#define NN (2 * HH)        // 1024 output channels of the GEMM
#define KK DD              // 512 (both layers: D = H = 512)

// ---------------- scratch (__device__ globals; no allocation) ----------------
__device__ float g_gh[(size_t)MM * NN];   // GEMM output  (128 MB)
__device__ float g_a [(size_t)MM * HH];   // coeff  (1-z) ( 64 MB)
__device__ float g_zg[(size_t)MM * HH];   // z * g(hidden)( 64 MB)
__device__ float g_h1[(size_t)MM * HH];   // layer-1 seq  ( 64 MB)

// ---------------- SGEMM:  C[M,N] = A[M,K] * W[N,K]^T + bias ----------------
#define BM 128
#define BN 128
#define BK 16

__global__ __launch_bounds__(256) void sgemm_bias_kernel(
    const float* __restrict__ A,    // M x K row-major
    const float* __restrict__ W,    // N x K row-major
    const float* __restrict__ bias, // N
    float* __restrict__ C,          // M x N row-major
    int M, int N, int K)
{
    __shared__ float As[BK][BM + 4];
    __shared__ float Bs[BK][BN + 4];

    const int tid = threadIdx.x;
    const int tx  = tid & 15;   // 0..15
    const int ty  = tid >> 4;   // 0..15
    const int m0  = blockIdx.y * BM;
    const int n0  = blockIdx.x * BN;

    const int lr = tid >> 2;          // 0..63 loader row
    const int lk = (tid & 3) * 4;     // 0,4,8,12 loader k-offset

    float acc[8][8];
#pragma unroll
    for (int i = 0; i < 8; ++i)
#pragma unroll
        for (int j = 0; j < 8; ++j) acc[i][j] = 0.f;

    for (int k0 = 0; k0 < K; k0 += BK) {
        float4 a0 = *(const float4*)(A + (size_t)(m0 + lr)      * K + k0 + lk);
        float4 a1 = *(const float4*)(A + (size_t)(m0 + lr + 64) * K + k0 + lk);
        float4 b0 = *(const float4*)(W + (size_t)(n0 + lr)      * K + k0 + lk);
        float4 b1 = *(const float4*)(W + (size_t)(n0 + lr + 64) * K + k0 + lk);

        As[lk + 0][lr]      = a0.x; As[lk + 1][lr]      = a0.y;
        As[lk + 2][lr]      = a0.z; As[lk + 3][lr]      = a0.w;
        As[lk + 0][lr + 64] = a1.x; As[lk + 1][lr + 64] = a1.y;
        As[lk + 2][lr + 64] = a1.z; As[lk + 3][lr + 64] = a1.w;
        Bs[lk + 0][lr]      = b0.x; Bs[lk + 1][lr]      = b0.y;
        Bs[lk + 2][lr]      = b0.z; Bs[lk + 3][lr]      = b0.w;
        Bs[lk + 0][lr + 64] = b1.x; Bs[lk + 1][lr + 64] = b1.y;
        Bs[lk + 2][lr + 64] = b1.z; Bs[lk + 3][lr + 64] = b1.w;
        __syncthreads();

#pragma unroll
        for (int k = 0; k < BK; ++k) {
            float ar[8], br[8];
#pragma unroll
            for (int j = 0; j < 4; ++j) {
                ar[j]     = As[k][ty * 4 + j];
                ar[4 + j] = As[k][64 + ty * 4 + j];
                br[j]     = Bs[k][tx * 4 + j];
                br[4 + j] = Bs[k][64 + tx * 4 + j];
            }
#pragma unroll
            for (int i = 0; i < 8; ++i)
#pragma unroll
                for (int j = 0; j < 8; ++j)
                    acc[i][j] = fmaf(ar[i], br[j], acc[i][j]);
        }
        __syncthreads();
    }

    // epilogue: add bias, store (vectorized float4)
#pragma unroll
    for (int i = 0; i < 8; ++i) {
        const int m = m0 + ((i < 4) ? (ty * 4 + i) : (64 + ty * 4 + (i - 4)));
        float* crow = C + (size_t)m * N;
#pragma unroll
        for (int jg = 0; jg < 2; ++jg) {
            const int nb = n0 + ((jg == 0) ? (tx * 4) : (64 + tx * 4));
            float4 v;
            v.x = acc[i][jg * 4 + 0] + bias[nb + 0];
            v.y = acc[i][jg * 4 + 1] + bias[nb + 1];
            v.z = acc[i][jg * 4 + 2] + bias[nb + 2];
            v.w = acc[i][jg * 4 + 3] + bias[nb + 3];
            *(float4*)(crow + nb) = v;
        }
    }
}

// ---------------- activation: gh -> (coeff, z*g) ----------------
__global__ __launch_bounds__(256) void act_kernel(
    const float* __restrict__ gh,  // M x 2H
    float* __restrict__ a_out,     // M x H  : 1 - z = sigmoid(-gate)
    float* __restrict__ zg_out)    // M x H  : z * g(hidden)
{
    const int i = blockIdx.x * blockDim.x + threadIdx.x;  // over M*H
    const int m = i >> 9;           // /512
    const int c = i & 511;
    const float gate = gh[(size_t)m * NN + c];
    const float hid  = gh[(size_t)m * NN + HH + c];
    const float z    = 1.f / (1.f + expf(-gate));   // sigmoid(gate)
    const float co   = 1.f / (1.f + expf(gate));    // sigmoid(-gate) = 1-z
    const float g    = (hid >= 0.f) ? (hid + 0.5f) : (1.f / (1.f + expf(-hid)));
    a_out[i]  = co;
    zg_out[i] = z * g;
}

// ---------------- sequential scan over S per (batch, channel) ----------------
__global__ __launch_bounds__(HH) void scan_kernel(
    const float* __restrict__ a,
    const float* __restrict__ zg,
    float* __restrict__ out,       // B x S x H
    float* __restrict__ hid_out)   // B x H (last step)
{
    const int b = blockIdx.x;
    const int h = threadIdx.x;
    const size_t base = (size_t)b * SS * HH + h;
    float hv = 0.5f;
#pragma unroll 8
    for (int s = 0; s < SS; ++s) {
        const size_t idx = base + (size_t)s * HH;
        hv = fmaf(a[idx], hv, zg[idx]);
        out[idx] = hv;
    }
    hid_out[b * HH + h] = hv;
}

// ---------------- launch ----------------
extern "C" void kernel_launch(void* const* d_in, const int* in_sizes, int n_in,
                              void* d_out, int out_size)
{
    (void)in_sizes; (void)n_in; (void)out_size;
    const float* x  = (const float*)d_in[0];
    const float* w0 = (const float*)d_in[1];
    const float* b0 = (const float*)d_in[2];
    const float* w1 = (const float*)d_in[3];
    const float* b1 = (const float*)d_in[4];
    float* out = (float*)d_out;

    float *gh, *ab, *zgb, *h1;
    cudaGetSymbolAddress((void**)&gh,  g_gh);
    cudaGetSymbolAddress((void**)&ab,  g_a);
    cudaGetSymbolAddress((void**)&zgb, g_zg);
    cudaGetSymbolAddress((void**)&h1,  g_h1);

    float* seq_out   = out;                              // (B,S,H)
    float* hid_base  = out + (size_t)MM * HH;            // (2,B,1,H)

    const dim3 ggrid(NN / BN, MM / BM);                  // (8, 256)
    const int act_blocks = (MM * HH) / 256;

    // Layer 1
    sgemm_bias_kernel<<<ggrid, 256>>>(x, w0, b0, gh, MM, NN, KK);
    act_kernel<<<act_blocks, 256>>>(gh, ab, zgb);
    scan_kernel<<<BB, HH>>>(ab, zgb, h1, hid_base);      // last hidden layer 1

    // Layer 2
    sgemm_bias_kernel<<<ggrid, 256>>>(h1, w1, b1, gh, MM, NN, KK);
    act_kernel<<<act_blocks, 256>>>(gh, ab, zgb);
    scan_kernel<<<BB, HH>>>(ab, zgb, seq_out, hid_base + BB * HH); // layer 2
}

// round 7
// speedup vs baseline: 2.6461x; 2.6461x over previous
#include <cuda_runtime.h>
#include <cuda_bf16.h>
#include <cstdint>
#include <math.h>

// Problem constants
#define BB 8
#define SS 4096
#define DD 512
#define HH 512
#define MM (BB * SS)       // 32768 rows
#define NN (2 * HH)        // 1024 GEMM output channels
#define KK 512

// scan chunking
#define NCH 64
#define CH  (SS / NCH)     // 64

// ---------------- scratch (__device__ globals; no allocation) ----------------
__device__ float g_gh[(size_t)MM * NN];     // GEMM output (128 MB)
__device__ __nv_bfloat16 g_ahi[(size_t)MM * KK];
__device__ __nv_bfloat16 g_alo[(size_t)MM * KK];
__device__ __nv_bfloat16 g_whi[(size_t)NN * KK];
__device__ __nv_bfloat16 g_wlo[(size_t)NN * KK];
__device__ float g_sA[BB * NCH * HH];
__device__ float g_sB[BB * NCH * HH];
__device__ float g_sE[BB * NCH * HH];

// ---------------- PTX helpers (plain sm_80+ features only) ----------------
__device__ __forceinline__ uint32_t smem_u32(const void* p) {
    uint32_t a;
    asm("{ .reg .u64 t; cvta.to.shared.u64 t, %1; cvt.u32.u64 %0, t; }" : "=r"(a) : "l"(p));
    return a;
}
__device__ __forceinline__ void cp_async16(uint32_t dst, const void* src) {
    asm volatile("cp.async.cg.shared.global [%0], [%1], 16;" :: "r"(dst), "l"(src));
}
#define CP_COMMIT() asm volatile("cp.async.commit_group;" ::: "memory")
#define CP_WAIT(n)  asm volatile("cp.async.wait_group %0;" :: "n"(n) : "memory")

__device__ __forceinline__ void ldsm4(uint32_t* r, uint32_t addr) {
    asm volatile("ldmatrix.sync.aligned.m8n8.x4.shared.b16 {%0,%1,%2,%3}, [%4];"
        : "=r"(r[0]), "=r"(r[1]), "=r"(r[2]), "=r"(r[3]) : "r"(addr));
}
__device__ __forceinline__ void mma_bf16(float& d0, float& d1, float& d2, float& d3,
                                         const uint32_t* a, const uint32_t* b) {
    asm volatile("mma.sync.aligned.m16n8k16.row.col.f32.bf16.bf16.f32 "
        "{%0,%1,%2,%3}, {%4,%5,%6,%7}, {%8,%9}, {%0,%1,%2,%3};"
        : "+f"(d0), "+f"(d1), "+f"(d2), "+f"(d3)
        : "r"(a[0]), "r"(a[1]), "r"(a[2]), "r"(a[3]), "r"(b[0]), "r"(b[1]));
}

__device__ __forceinline__ uint32_t sw64(uint32_t off) {   // 64B-row swizzle
    return off ^ ((off >> 3) & 0x30);
}

// ---------------- fp32 -> bf16 hi/lo split ----------------
__global__ __launch_bounds__(256) void split_kernel(
    const float* __restrict__ src, __nv_bfloat16* __restrict__ hi,
    __nv_bfloat16* __restrict__ lo, int n2)
{
    int i = blockIdx.x * blockDim.x + threadIdx.x;
    if (i >= n2) return;
    float2 v = ((const float2*)src)[i];
    __nv_bfloat16 hx = __float2bfloat16(v.x);
    __nv_bfloat16 hy = __float2bfloat16(v.y);
    __nv_bfloat162 h2; h2.x = hx; h2.y = hy;
    __nv_bfloat162 l2;
    l2.x = __float2bfloat16(v.x - __bfloat162float(hx));
    l2.y = __float2bfloat16(v.y - __bfloat162float(hy));
    ((__nv_bfloat162*)hi)[i] = h2;
    ((__nv_bfloat162*)lo)[i] = l2;
}

// ---------------- HMMA bf16 split GEMM: C[M,N] = A[M,K]*W[N,K]^T + bias ----------------
// CTA tile 128x128, BK=32, 8 warps (2x4), warp tile 64x32, double-buffered cp.async.
#define BK 32
#define TILEB  (128 * 64)            // one operand tile: 128 rows x 64B (32 bf16)
#define STAGEB (4 * TILEB)           // Ahi, Alo, Bhi, Blo = 32KB
#define GSMEM  (2 * STAGEB)          // 64KB

__global__ __launch_bounds__(256, 1) void gemm_hmma_kernel(
    const __nv_bfloat16* __restrict__ Ahi, const __nv_bfloat16* __restrict__ Alo,
    const __nv_bfloat16* __restrict__ Whi, const __nv_bfloat16* __restrict__ Wlo,
    const float* __restrict__ bias, float* __restrict__ C)
{
    extern __shared__ char smem[];
    const uint32_t sm0 = smem_u32(smem);

    const int tid = threadIdx.x;
    const int lane = tid & 31;
    const int wid = tid >> 5;
    const int wm = wid & 1;           // warp m row (0..1)
    const int wn = wid >> 1;          // warp n col (0..3)
    const int m0 = blockIdx.y * 128;
    const int n0 = blockIdx.x * 128;

    float acc[4][4][4];
#pragma unroll
    for (int i = 0; i < 4; ++i)
#pragma unroll
        for (int j = 0; j < 4; ++j)
#pragma unroll
            for (int k = 0; k < 4; ++k) acc[i][j][k] = 0.f;

    // loader: per tile 512 x 16B transfers; thread does j=tid and j=tid+256
    auto load_stage = [&](int s, int kc) {
        const uint32_t st = sm0 + s * STAGEB;
        const int k0 = kc * BK;
#pragma unroll
        for (int half = 0; half < 2; ++half) {
            const int j = tid + half * 256;
            const int r = j >> 2, c16 = (j & 3);
            const uint32_t dof = sw64((uint32_t)(r * 64 + c16 * 16));
            const size_t ga = (size_t)(m0 + r) * KK + k0 + c16 * 8;
            const size_t gb = (size_t)(n0 + r) * KK + k0 + c16 * 8;
            cp_async16(st + 0 * TILEB + dof, Ahi + ga);
            cp_async16(st + 1 * TILEB + dof, Alo + ga);
            cp_async16(st + 2 * TILEB + dof, Whi + gb);
            cp_async16(st + 3 * TILEB + dof, Wlo + gb);
        }
    };

    load_stage(0, 0); CP_COMMIT();
    load_stage(1, 1); CP_COMMIT();

    const int NKC = KK / BK;          // 16
#pragma unroll 1
    for (int c = 0; c < NKC; ++c) {
        const int s = c & 1;
        CP_WAIT(1);
        __syncthreads();
        const uint32_t st = sm0 + s * STAGEB;

#pragma unroll
        for (int ks = 0; ks < 2; ++ks) {
            // ---- A fragments (m16k16 per m-tile); x4 lane-groups -> a0..a3 order ----
            uint32_t ah[4][4], al[4][4], bh[4][2], bl[4][2];
#pragma unroll
            for (int mt = 0; mt < 4; ++mt) {
                const int mrow = wm * 64 + mt * 16 + (lane & 7) + ((lane >> 3) & 1) * 8;
                const int kcol = ks * 16 + (lane >> 4) * 8;
                const uint32_t off = sw64((uint32_t)(mrow * 64 + kcol * 2));
                ldsm4(ah[mt], st + 0 * TILEB + off);
                ldsm4(al[mt], st + 1 * TILEB + off);
            }
            // ---- B fragments: W is [n][k] == col-layout B; NON-trans ldmatrix.
            // One x4 covers n16 x k16: r4[0]=n0-7/k0-7, r4[1]=n0-7/k8-15,
            //                          r4[2]=n8-15/k0-7, r4[3]=n8-15/k8-15 ----
#pragma unroll
            for (int p = 0; p < 2; ++p) {
                const int nrow = wn * 32 + p * 16 + ((lane >> 4) & 1) * 8 + (lane & 7);
                const int kcol = ks * 16 + ((lane >> 3) & 1) * 8;
                const uint32_t off = sw64((uint32_t)(nrow * 64 + kcol * 2));
                uint32_t r4[4];
                ldsm4(r4, st + 2 * TILEB + off);
                bh[2 * p][0] = r4[0]; bh[2 * p][1] = r4[1];
                bh[2 * p + 1][0] = r4[2]; bh[2 * p + 1][1] = r4[3];
                ldsm4(r4, st + 3 * TILEB + off);
                bl[2 * p][0] = r4[0]; bl[2 * p][1] = r4[1];
                bl[2 * p + 1][0] = r4[2]; bl[2 * p + 1][1] = r4[3];
            }
            // ---- 3-pass MMA: hi*hi + hi*lo + lo*hi ----
#pragma unroll
            for (int mt = 0; mt < 4; ++mt)
#pragma unroll
                for (int nt = 0; nt < 4; ++nt) {
                    mma_bf16(acc[mt][nt][0], acc[mt][nt][1], acc[mt][nt][2], acc[mt][nt][3], ah[mt], bh[nt]);
                    mma_bf16(acc[mt][nt][0], acc[mt][nt][1], acc[mt][nt][2], acc[mt][nt][3], ah[mt], bl[nt]);
                    mma_bf16(acc[mt][nt][0], acc[mt][nt][1], acc[mt][nt][2], acc[mt][nt][3], al[mt], bh[nt]);
                }
        }
        __syncthreads();
        if (c + 2 < NKC) { load_stage(s, c + 2); CP_COMMIT(); }
    }

    // epilogue: add bias, store
    const int gid = lane >> 2, tig = lane & 3;
#pragma unroll
    for (int mt = 0; mt < 4; ++mt) {
#pragma unroll
        for (int nt = 0; nt < 4; ++nt) {
            const int m = m0 + wm * 64 + mt * 16 + gid;
            const int n = n0 + wn * 32 + nt * 8 + tig * 2;
            const float b0v = bias[n], b1v = bias[n + 1];
            float2 v0 = { acc[mt][nt][0] + b0v, acc[mt][nt][1] + b1v };
            float2 v1 = { acc[mt][nt][2] + b0v, acc[mt][nt][3] + b1v };
            *(float2*)(C + (size_t)m * NN + n)       = v0;
            *(float2*)(C + (size_t)(m + 8) * NN + n) = v1;
        }
    }
}

// ---------------- activation math (matches reference) ----------------
__device__ __forceinline__ void act_compute(float gate, float hid, float& a, float& zg) {
    const float z  = 1.f / (1.f + __expf(-gate));   // sigmoid(gate)
    a = 1.f / (1.f + __expf(gate));                 // sigmoid(-gate) = 1 - z
    const float g  = (hid >= 0.f) ? (hid + 0.5f) : (1.f / (1.f + __expf(-hid)));
    zg = z * g;
}

// ---------------- chunked scan over gh (act recomputed on the fly) ----------------
__global__ __launch_bounds__(HH) void scan_pass1(
    const float* __restrict__ gh, float* __restrict__ Ac, float* __restrict__ Bc)
{
    const int c = blockIdx.x, b = blockIdx.y, h = threadIdx.x;
    const size_t row0 = (size_t)b * SS + (size_t)c * CH;
    float A = 1.f, Bv = 0.f;
#pragma unroll 4
    for (int s = 0; s < CH; ++s) {
        const size_t ro = (row0 + s) * NN;
        float av, zg;
        act_compute(gh[ro + h], gh[ro + HH + h], av, zg);
        A *= av;
        Bv = fmaf(av, Bv, zg);
    }
    Ac[(b * NCH + c) * HH + h] = A;
    Bc[(b * NCH + c) * HH + h] = Bv;
}

__global__ __launch_bounds__(HH) void scan_pass2(
    const float* __restrict__ Ac, const float* __restrict__ Bc, float* __restrict__ entry)
{
    const int b = blockIdx.x, h = threadIdx.x;
    float hv = 0.5f;
#pragma unroll 8
    for (int c = 0; c < NCH; ++c) {
        const int i = (b * NCH + c) * HH + h;
        entry[i] = hv;
        hv = fmaf(Ac[i], hv, Bc[i]);
    }
}

// MODE 0: write fp32 out. MODE 1: write bf16 hi/lo split (feeds next GEMM).
template <int MODE>
__global__ __launch_bounds__(HH) void scan_pass3(
    const float* __restrict__ gh, const float* __restrict__ entry,
    float* __restrict__ out, __nv_bfloat16* __restrict__ hi, __nv_bfloat16* __restrict__ lo,
    float* __restrict__ hid_out)
{
    const int c = blockIdx.x, b = blockIdx.y, h = threadIdx.x;
    const size_t row0 = (size_t)b * SS + (size_t)c * CH;
    float hv = entry[(b * NCH + c) * HH + h];
#pragma unroll 4
    for (int s = 0; s < CH; ++s) {
        const size_t ro = (row0 + s) * NN;
        float av, zg;
        act_compute(gh[ro + h], gh[ro + HH + h], av, zg);
        hv = fmaf(av, hv, zg);
        const size_t oi = (row0 + s) * HH + h;
        if (MODE == 0) {
            out[oi] = hv;
        } else {
            __nv_bfloat16 hx = __float2bfloat16(hv);
            hi[oi] = hx;
            lo[oi] = __float2bfloat16(hv - __bfloat162float(hx));
        }
    }
    if (c == NCH - 1) hid_out[b * HH + h] = hv;
}

// ---------------- launch ----------------
extern "C" void kernel_launch(void* const* d_in, const int* in_sizes, int n_in,
                              void* d_out, int out_size)
{
    (void)in_sizes; (void)n_in; (void)out_size;
    const float* x  = (const float*)d_in[0];
    const float* w0 = (const float*)d_in[1];
    const float* b0 = (const float*)d_in[2];
    const float* w1 = (const float*)d_in[3];
    const float* b1 = (const float*)d_in[4];
    float* out = (float*)d_out;

    float *gh, *sA, *sB, *sE;
    __nv_bfloat16 *ahi, *alo, *whi, *wlo;
    cudaGetSymbolAddress((void**)&gh,  g_gh);
    cudaGetSymbolAddress((void**)&ahi, g_ahi);
    cudaGetSymbolAddress((void**)&alo, g_alo);
    cudaGetSymbolAddress((void**)&whi, g_whi);
    cudaGetSymbolAddress((void**)&wlo, g_wlo);
    cudaGetSymbolAddress((void**)&sA,  g_sA);
    cudaGetSymbolAddress((void**)&sB,  g_sB);
    cudaGetSymbolAddress((void**)&sE,  g_sE);

    cudaFuncSetAttribute(gemm_hmma_kernel, cudaFuncAttributeMaxDynamicSharedMemorySize, GSMEM);

    float* seq_out  = out;
    float* hid_base = out + (size_t)MM * HH;

    const dim3 ggrid(NN / 128, MM / 128);            // (8, 256)
    const dim3 sgrid(NCH, BB);
    const int splitA_blocks = (MM * KK / 2) / 256;   // 32768
    const int splitW_blocks = (NN * KK / 2) / 256;   // 1024

    // Layer 1
    split_kernel<<<splitA_blocks, 256>>>(x,  ahi, alo, MM * KK / 2);
    split_kernel<<<splitW_blocks, 256>>>(w0, whi, wlo, NN * KK / 2);
    gemm_hmma_kernel<<<ggrid, 256, GSMEM>>>(ahi, alo, whi, wlo, b0, gh);
    scan_pass1<<<sgrid, HH>>>(gh, sA, sB);
    scan_pass2<<<BB, HH>>>(sA, sB, sE);
    scan_pass3<1><<<sgrid, HH>>>(gh, sE, nullptr, ahi, alo, hid_base);     // layer-1 out -> bf16 split

    // Layer 2
    split_kernel<<<splitW_blocks, 256>>>(w1, whi, wlo, NN * KK / 2);
    gemm_hmma_kernel<<<ggrid, 256, GSMEM>>>(ahi, alo, whi, wlo, b1, gh);
    scan_pass1<<<sgrid, HH>>>(gh, sA, sB);
    scan_pass2<<<BB, HH>>>(sA, sB, sE);
    scan_pass3<0><<<sgrid, HH>>>(gh, sE, seq_out, nullptr, nullptr, hid_base + BB * HH);
}